// round 7
// baseline (speedup 1.0000x reference)
#include <cuda_runtime.h>

// Problem constants (fixed by setup_inputs)
#define B_ 16
#define A_ 9
#define H_ 128
#define W_ 128
#define S_ 2048.0f
// sigmoid(d) > 0.7  <=>  d > ln(7/3)
#define LOGIT_THRESH 0.84729786038720363f

#define TPB 128
#define WPT 8                  // w positions per thread
#define SLOTS 18               // useful float4 slots per thread
#define SLOTP 19               // padded stride (76 words % 32 = 12 -> conflict-free STS.128)

// Precomputed anchor table, (a, w) order: (acx, acy, aw, ah). 18 KB, L1/L2-hot.
// Built by a tiny prologue (the a*w*129 gather is lane-divergent; doing it
// per-block costs ~9us -- measured R4 vs R5).
__device__ float4 d_anc_tab[A_ * W_];

__global__ void build_anchor_tab(const float* __restrict__ anchor) {
    int t = blockIdx.x * blockDim.x + threadIdx.x;
    if (t >= A_ * W_) return;
    int a = t / W_;
    int w = t % W_;
    long row = (long)a * w * (W_ + 1);    // idx[a,w] = a*w*(W+1)
    const float* p = anchor + row * 6;
    d_anc_tab[t] = make_float4(p[2], p[3], p[4], p[5]);
}

// 8 w positions per thread: 12 input LDG.128 issued up-front (2x MLP vs R6),
// 8 L1-hot anchor LDG.128, results packed to float4 in padded smem, single
// barrier, 18-iteration fully coalesced streaming copy-out.
__global__ __launch_bounds__(TPB) void proposal_kernel(
    const float* __restrict__ cla,
    const float* __restrict__ reg,
    float* __restrict__ out)
{
    __shared__ float4 sOut[TPB * SLOTP];      // 38912 B

    const int W8  = W_ / WPT;       // 16 groups per row
    const int HW4 = (H_ * W_) / 4;  // 4096 float4 per channel plane

    int tid = threadIdx.x;
    int t = blockIdx.x * TPB + tid;
    int wq = t & (W8 - 1);
    int h  = (t / W8) & (H_ - 1);
    int a  = (t / (W8 * H_)) % A_;
    int b  =  t / (W8 * H_ * A_);
    int w0 = wq * WPT;

    int sp4 = (h * W_ + w0) >> 2;   // first of 2 consecutive float4 per channel

    const float4* cla4 = (const float4*)cla;
    const float4* reg4 = (const float4*)reg;

    // ---- all 12 input loads up-front (independent -> deep MLP) ----
    int cbase = (b * 2 * A_ + 2 * a) * HW4 + sp4;
    float4 v_c0a = cla4[cbase];
    float4 v_c0b = cla4[cbase + 1];
    float4 v_c1a = cla4[cbase + HW4];
    float4 v_c1b = cla4[cbase + HW4 + 1];

    int rbase = (b * 4 * A_ + 4 * a) * HW4 + sp4;
    float4 v_txa = reg4[rbase + 0 * HW4], v_txb = reg4[rbase + 0 * HW4 + 1];
    float4 v_tya = reg4[rbase + 1 * HW4], v_tyb = reg4[rbase + 1 * HW4 + 1];
    float4 v_twa = reg4[rbase + 2 * HW4], v_twb = reg4[rbase + 2 * HW4 + 1];
    float4 v_tha = reg4[rbase + 3 * HW4], v_thb = reg4[rbase + 3 * HW4 + 1];

    // 8 consecutive anchor entries (lane-consecutive coalesced, L1-hot)
    const float4* tab = d_anc_tab + a * W_ + w0;
    float4 anca[WPT];
    #pragma unroll
    for (int i = 0; i < WPT; i++) anca[i] = tab[i];

    float c0[WPT] = {v_c0a.x, v_c0a.y, v_c0a.z, v_c0a.w, v_c0b.x, v_c0b.y, v_c0b.z, v_c0b.w};
    float c1[WPT] = {v_c1a.x, v_c1a.y, v_c1a.z, v_c1a.w, v_c1b.x, v_c1b.y, v_c1b.z, v_c1b.w};
    float tx[WPT] = {v_txa.x, v_txa.y, v_txa.z, v_txa.w, v_txb.x, v_txb.y, v_txb.z, v_txb.w};
    float ty[WPT] = {v_tya.x, v_tya.y, v_tya.z, v_tya.w, v_tyb.x, v_tyb.y, v_tyb.z, v_tyb.w};
    float tw[WPT] = {v_twa.x, v_twa.y, v_twa.z, v_twa.w, v_twb.x, v_twb.y, v_twb.z, v_twb.w};
    float th[WPT] = {v_tha.x, v_tha.y, v_tha.z, v_tha.w, v_thb.x, v_thb.y, v_thb.z, v_thb.w};

    float4* my = sOut + tid * SLOTP;

    // Two halves of 4 anchors; each half packs 36 floats into 9 float4 slots.
    #pragma unroll
    for (int half = 0; half < 2; half++) {
        float f[4][9];
        #pragma unroll
        for (int j = 0; j < 4; j++) {
            int i = half * 4 + j;
            float acx = anca[i].x, acy = anca[i].y, aw = anca[i].z, ah = anca[i].w;

            float cxn = fmaf(tx[i], aw, acx);
            float cyn = fmaf(ty[i], ah, acy);
            float wvn = expf(tw[i]) * aw;
            float hvn = expf(th[i]) * ah;

            float ltxn = cxn - 0.5f * wvn;
            float ltyn = cyn - 0.5f * hvn;
            float rbxn = cxn + 0.5f * wvn;
            float rbyn = cyn + 0.5f * hvn;

            bool valid = ((c1[i] - c0[i]) > LOGIT_THRESH)
                         && (ltxn >= 0.0f) && (ltyn >= 0.0f)
                         && (rbxn <= 1.0f) && (rbyn <= 1.0f);
            float m = valid ? 1.0f : 0.0f;

            f[j][0] = (ltxn * S_) * m;
            f[j][1] = (ltyn * S_) * m;
            f[j][2] = (rbxn * S_) * m;
            f[j][3] = (rbyn * S_) * m;
            f[j][4] = cxn * m;
            f[j][5] = cyn * m;
            f[j][6] = wvn * m;
            f[j][7] = hvn * m;
            f[j][8] = m;
        }
        float4* mh = my + half * 9;
        mh[0] = make_float4(f[0][0], f[0][1], f[0][2], f[0][3]);
        mh[1] = make_float4(f[0][4], f[0][5], f[0][6], f[0][7]);
        mh[2] = make_float4(f[0][8], f[1][0], f[1][1], f[1][2]);
        mh[3] = make_float4(f[1][3], f[1][4], f[1][5], f[1][6]);
        mh[4] = make_float4(f[1][7], f[1][8], f[2][0], f[2][1]);
        mh[5] = make_float4(f[2][2], f[2][3], f[2][4], f[2][5]);
        mh[6] = make_float4(f[2][6], f[2][7], f[2][8], f[3][0]);
        mh[7] = make_float4(f[3][1], f[3][2], f[3][3], f[3][4]);
        mh[8] = make_float4(f[3][5], f[3][6], f[3][7], f[3][8]);
    }

    __syncthreads();

    // Coalesced vectorized copy-out: linear output float4 index s maps to
    // padded slot s + s/SLOTS. Lane-consecutive 512B STG.128, streaming.
    float4* o4 = (float4*)out + (size_t)blockIdx.x * (TPB * SLOTS);
    #pragma unroll
    for (int it = 0; it < SLOTS; it++) {
        int s = tid + it * TPB;
        __stcs(o4 + s, sOut[s + s / SLOTS]);
    }
}

extern "C" void kernel_launch(void* const* d_in, const int* in_sizes, int n_in,
                              void* d_out, int out_size) {
    const float* cla    = (const float*)d_in[0];
    const float* reg    = (const float*)d_in[1];
    const float* anchor = (const float*)d_in[2];
    float* out = (float*)d_out;

    build_anchor_tab<<<(A_ * W_ + 127) / 128, 128>>>(anchor);

    int total_grp = B_ * A_ * H_ * (W_ / WPT);   // 294912
    proposal_kernel<<<total_grp / TPB, TPB>>>(cla, reg, out);
}

// round 8
// speedup vs baseline: 1.0441x; 1.0441x over previous
#include <cuda_runtime.h>

// Problem constants (fixed by setup_inputs)
#define B_ 16
#define A_ 9
#define H_ 128
#define W_ 128
#define S_ 2048.0f
// sigmoid(d) > 0.7  <=>  d > ln(7/3)
#define LOGIT_THRESH 0.84729786038720363f

#define TPB 128

// Precomputed anchor table, (a, w) order: (acx, acy, aw, ah). 18 KB, L1/L2-hot.
// Built by a tiny prologue (the a*w*129 gather is lane-divergent; doing it
// per-block costs ~9us -- measured R4 vs R5).
__device__ float4 d_anc_tab[A_ * W_];

__global__ void build_anchor_tab(const float* __restrict__ anchor) {
    int t = blockIdx.x * blockDim.x + threadIdx.x;
    if (t >= A_ * W_) return;
    int a = t / W_;
    int w = t % W_;
    long row = (long)a * w * (W_ + 1);    // idx[a,w] = a*w*(W+1)
    const float* p = anchor + row * 6;
    d_anc_tab[t] = make_float4(p[2], p[3], p[4], p[5]);
}

// R6 structure (best-measured), with min-blocks hint to cap regs at 42 and
// lift occupancy from ~55% to ~75% (12 blocks x 18.4KB smem = 221KB <= 228KB).
// Kernel is latency-bound (no pipe >60%); more warps in flight is the lever.
__global__ __launch_bounds__(TPB, 12) void proposal_kernel(
    const float* __restrict__ cla,
    const float* __restrict__ reg,
    float* __restrict__ out)
{
    // Output staging: TPB threads x 9 float4 slots, output-linear layout.
    __shared__ float4 sOut[TPB * 9];          // 18432 B

    const int WQ  = W_ / 4;         // 32
    const int HW4 = (H_ * W_) / 4;  // 4096 float4 per channel plane

    int tid = threadIdx.x;
    int t = blockIdx.x * TPB + tid;
    int wq = t & (WQ - 1);                    // == tid & 31
    int h  = (t / WQ) & (H_ - 1);
    int a  = (t / (WQ * H_)) % A_;            // uniform within a block
    int b  =  t / (WQ * H_ * A_);
    int w0 = wq * 4;

    int sp4 = (h * W_ + w0) >> 2;

    const float4* cla4 = (const float4*)cla;
    const float4* reg4 = (const float4*)reg;

    int cbase = (b * 2 * A_ + 2 * a) * HW4 + sp4;
    float4 v_c0 = cla4[cbase];
    float4 v_c1 = cla4[cbase + HW4];

    int rbase = (b * 4 * A_ + 4 * a) * HW4 + sp4;
    float4 v_tx = reg4[rbase + 0 * HW4];
    float4 v_ty = reg4[rbase + 1 * HW4];
    float4 v_tw = reg4[rbase + 2 * HW4];
    float4 v_th = reg4[rbase + 3 * HW4];

    // Anchor entries: 4 consecutive float4s, lane-consecutive across the warp
    // (coalesced LDG.128 from the 18KB hot table).
    const float4* tab = d_anc_tab + a * W_ + w0;
    float4 anca[4] = {tab[0], tab[1], tab[2], tab[3]};

    float c0a[4] = {v_c0.x, v_c0.y, v_c0.z, v_c0.w};
    float c1a[4] = {v_c1.x, v_c1.y, v_c1.z, v_c1.w};
    float txa[4] = {v_tx.x, v_tx.y, v_tx.z, v_tx.w};
    float tya[4] = {v_ty.x, v_ty.y, v_ty.z, v_ty.w};
    float twa[4] = {v_tw.x, v_tw.y, v_tw.z, v_tw.w};
    float tha[4] = {v_th.x, v_th.y, v_th.z, v_th.w};

    float4* my = sOut + tid * 9;   // slot stride 9 float4 = 36 words: conflict-free STS.128

    float f[4][9];
    #pragma unroll
    for (int i = 0; i < 4; i++) {
        float acx = anca[i].x, acy = anca[i].y, aw = anca[i].z, ah = anca[i].w;

        float cxn = fmaf(txa[i], aw, acx);
        float cyn = fmaf(tya[i], ah, acy);
        float wvn = expf(twa[i]) * aw;
        float hvn = expf(tha[i]) * ah;

        float ltxn = cxn - 0.5f * wvn;
        float ltyn = cyn - 0.5f * hvn;
        float rbxn = cxn + 0.5f * wvn;
        float rbyn = cyn + 0.5f * hvn;

        // fg > 0.7  <=>  (c1 - c0) > ln(7/3)
        bool valid = ((c1a[i] - c0a[i]) > LOGIT_THRESH)
                     && (ltxn >= 0.0f) && (ltyn >= 0.0f)
                     && (rbxn <= 1.0f) && (rbyn <= 1.0f);
        float m = valid ? 1.0f : 0.0f;

        f[i][0] = (ltxn * S_) * m;
        f[i][1] = (ltyn * S_) * m;
        f[i][2] = (rbxn * S_) * m;
        f[i][3] = (rbyn * S_) * m;
        f[i][4] = cxn * m;
        f[i][5] = cyn * m;
        f[i][6] = wvn * m;
        f[i][7] = hvn * m;
        f[i][8] = m;
    }

    // Pack 4x9 floats into 9 float4 smem slots (output-linear order).
    my[0] = make_float4(f[0][0], f[0][1], f[0][2], f[0][3]);
    my[1] = make_float4(f[0][4], f[0][5], f[0][6], f[0][7]);
    my[2] = make_float4(f[0][8], f[1][0], f[1][1], f[1][2]);
    my[3] = make_float4(f[1][3], f[1][4], f[1][5], f[1][6]);
    my[4] = make_float4(f[1][7], f[1][8], f[2][0], f[2][1]);
    my[5] = make_float4(f[2][2], f[2][3], f[2][4], f[2][5]);
    my[6] = make_float4(f[2][6], f[2][7], f[2][8], f[3][0]);
    my[7] = make_float4(f[3][1], f[3][2], f[3][3], f[3][4]);
    my[8] = make_float4(f[3][5], f[3][6], f[3][7], f[3][8]);

    __syncthreads();

    // Coalesced vectorized copy-out: lane-consecutive float4, streaming stores.
    float4* o4 = (float4*)out + (size_t)blockIdx.x * (TPB * 9);
    #pragma unroll
    for (int it = 0; it < 9; it++) {
        int s = tid + it * TPB;
        __stcs(o4 + s, sOut[s]);   // LDS.128 conflict-free, STG.128 512B/warp
    }
}

extern "C" void kernel_launch(void* const* d_in, const int* in_sizes, int n_in,
                              void* d_out, int out_size) {
    const float* cla    = (const float*)d_in[0];
    const float* reg    = (const float*)d_in[1];
    const float* anchor = (const float*)d_in[2];
    float* out = (float*)d_out;

    build_anchor_tab<<<(A_ * W_ + 127) / 128, 128>>>(anchor);

    int total_vec = B_ * A_ * H_ * (W_ / 4);   // 589824
    proposal_kernel<<<total_vec / TPB, TPB>>>(cla, reg, out);
}

// round 9
// speedup vs baseline: 1.2129x; 1.1616x over previous
#include <cuda_runtime.h>
#include <cstdint>

// Problem constants (fixed by setup_inputs)
#define B_ 16
#define A_ 9
#define H_ 128
#define W_ 128
#define S_ 2048.0f
// sigmoid(d) > 0.7  <=>  d > ln(7/3)
#define LOGIT_THRESH 0.84729786038720363f

#define TPB 128
#define BLK_BYTES (TPB * 9 * 16)   // 18432 B contiguous output per block

// Precomputed anchor table, (a, w) order: (acx, acy, aw, ah). 18 KB, L1/L2-hot.
// (per-block a*w*129 gather is lane-divergent: costs ~9us, measured R4 vs R5)
__device__ float4 d_anc_tab[A_ * W_];

__global__ void build_anchor_tab(const float* __restrict__ anchor) {
    int t = blockIdx.x * blockDim.x + threadIdx.x;
    if (t >= A_ * W_) return;
    int a = t / W_;
    int w = t % W_;
    long row = (long)a * w * (W_ + 1);    // idx[a,w] = a*w*(W+1)
    const float* p = anchor + row * 6;
    d_anc_tab[t] = make_float4(p[2], p[3], p[4], p[5]);
}

__device__ __forceinline__ uint32_t smem_u32(const void* p) {
    uint32_t a;
    asm("{ .reg .u64 t; cvta.to.shared.u64 t, %1; cvt.u32.u64 %0, t; }"
        : "=r"(a) : "l"(p));
    return a;
}

// R6 compute structure; copy-out replaced by a single TMA 1-D bulk store.
// Removes ~72 L1 wavefronts/warp (all LDS+STG of the copy loop) from the
// SM's LSU path -- the TMA engine drains smem->gmem asynchronously.
__global__ __launch_bounds__(TPB) void proposal_kernel(
    const float* __restrict__ cla,
    const float* __restrict__ reg,
    float* __restrict__ out)
{
    // Output staging: TPB threads x 9 float4 slots, output-linear layout.
    __shared__ __align__(128) float4 sOut[TPB * 9];   // 18432 B

    const int WQ  = W_ / 4;         // 32
    const int HW4 = (H_ * W_) / 4;  // 4096 float4 per channel plane

    int tid = threadIdx.x;
    int t = blockIdx.x * TPB + tid;
    int wq = t & (WQ - 1);                    // == tid & 31
    int h  = (t / WQ) & (H_ - 1);
    int a  = (t / (WQ * H_)) % A_;            // uniform within a block
    int b  =  t / (WQ * H_ * A_);
    int w0 = wq * 4;

    int sp4 = (h * W_ + w0) >> 2;

    const float4* cla4 = (const float4*)cla;
    const float4* reg4 = (const float4*)reg;

    int cbase = (b * 2 * A_ + 2 * a) * HW4 + sp4;
    float4 v_c0 = cla4[cbase];
    float4 v_c1 = cla4[cbase + HW4];

    int rbase = (b * 4 * A_ + 4 * a) * HW4 + sp4;
    float4 v_tx = reg4[rbase + 0 * HW4];
    float4 v_ty = reg4[rbase + 1 * HW4];
    float4 v_tw = reg4[rbase + 2 * HW4];
    float4 v_th = reg4[rbase + 3 * HW4];

    // Anchor entries: 4 consecutive float4s, lane-consecutive (L1-hot table).
    const float4* tab = d_anc_tab + a * W_ + w0;
    float4 anca[4] = {tab[0], tab[1], tab[2], tab[3]};

    float c0a[4] = {v_c0.x, v_c0.y, v_c0.z, v_c0.w};
    float c1a[4] = {v_c1.x, v_c1.y, v_c1.z, v_c1.w};
    float txa[4] = {v_tx.x, v_tx.y, v_tx.z, v_tx.w};
    float tya[4] = {v_ty.x, v_ty.y, v_ty.z, v_ty.w};
    float twa[4] = {v_tw.x, v_tw.y, v_tw.z, v_tw.w};
    float tha[4] = {v_th.x, v_th.y, v_th.z, v_th.w};

    float4* my = sOut + tid * 9;   // stride 36 words: conflict-free STS.128

    float f[4][9];
    #pragma unroll
    for (int i = 0; i < 4; i++) {
        float acx = anca[i].x, acy = anca[i].y, aw = anca[i].z, ah = anca[i].w;

        float cxn = fmaf(txa[i], aw, acx);
        float cyn = fmaf(tya[i], ah, acy);
        float wvn = expf(twa[i]) * aw;
        float hvn = expf(tha[i]) * ah;

        float ltxn = cxn - 0.5f * wvn;
        float ltyn = cyn - 0.5f * hvn;
        float rbxn = cxn + 0.5f * wvn;
        float rbyn = cyn + 0.5f * hvn;

        // fg > 0.7  <=>  (c1 - c0) > ln(7/3)
        bool valid = ((c1a[i] - c0a[i]) > LOGIT_THRESH)
                     && (ltxn >= 0.0f) && (ltyn >= 0.0f)
                     && (rbxn <= 1.0f) && (rbyn <= 1.0f);
        float m = valid ? 1.0f : 0.0f;

        f[i][0] = (ltxn * S_) * m;
        f[i][1] = (ltyn * S_) * m;
        f[i][2] = (rbxn * S_) * m;
        f[i][3] = (rbyn * S_) * m;
        f[i][4] = cxn * m;
        f[i][5] = cyn * m;
        f[i][6] = wvn * m;
        f[i][7] = hvn * m;
        f[i][8] = m;
    }

    // Pack 4x9 floats into 9 float4 smem slots (output-linear order).
    my[0] = make_float4(f[0][0], f[0][1], f[0][2], f[0][3]);
    my[1] = make_float4(f[0][4], f[0][5], f[0][6], f[0][7]);
    my[2] = make_float4(f[0][8], f[1][0], f[1][1], f[1][2]);
    my[3] = make_float4(f[1][3], f[1][4], f[1][5], f[1][6]);
    my[4] = make_float4(f[1][7], f[1][8], f[2][0], f[2][1]);
    my[5] = make_float4(f[2][2], f[2][3], f[2][4], f[2][5]);
    my[6] = make_float4(f[2][6], f[2][7], f[2][8], f[3][0]);
    my[7] = make_float4(f[3][1], f[3][2], f[3][3], f[3][4]);
    my[8] = make_float4(f[3][5], f[3][6], f[3][7], f[3][8]);

    __syncthreads();

    // Single TMA 1-D bulk store of the block's contiguous 18432B output.
    if (tid == 0) {
        // make generic-proxy STS results visible to the async proxy
        asm volatile("fence.proxy.async.shared::cta;" ::: "memory");
        uint32_t src = smem_u32(sOut);
        float* dst = out + (size_t)blockIdx.x * (TPB * 36);
        asm volatile(
            "cp.async.bulk.global.shared::cta.bulk_group [%0], [%1], %2;"
            :: "l"(dst), "r"(src), "r"((int)BLK_BYTES) : "memory");
        asm volatile("cp.async.bulk.commit_group;" ::: "memory");
        // hold smem alive until the TMA engine has READ it
        asm volatile("cp.async.bulk.wait_group.read 0;" ::: "memory");
    }
}

extern "C" void kernel_launch(void* const* d_in, const int* in_sizes, int n_in,
                              void* d_out, int out_size) {
    const float* cla    = (const float*)d_in[0];
    const float* reg    = (const float*)d_in[1];
    const float* anchor = (const float*)d_in[2];
    float* out = (float*)d_out;

    build_anchor_tab<<<(A_ * W_ + 127) / 128, 128>>>(anchor);

    int total_vec = B_ * A_ * H_ * (W_ / 4);   // 589824
    proposal_kernel<<<total_vec / TPB, TPB>>>(cla, reg, out);
}